// round 9
// baseline (speedup 1.0000x reference)
#include <cuda_runtime.h>
#include <cstdint>

#define T_DIM 4096
#define B_DIM 32
#define H_DIM 256
#define L_DIM 512
#define K_DIM 32
#define T_BLK 128

// Scratch (allocation-free contract: __device__ globals)
__device__ __align__(16) float g_kern[B_DIM * H_DIM * K_DIM];   // [b][h*K+k] fp32
__device__ __align__(16) float g_glob[B_DIM * H_DIM];           // (B,H)
__device__ __align__(16) float g_exp[T_DIM * B_DIM];            // exp(score+mask)
__device__ __align__(16) float g_part[(T_DIM / T_BLK) * B_DIM]; // partial exp sums

// ---- helpers ----
__device__ __forceinline__ float tanh_ap(float x) {
    float y; asm("tanh.approx.f32 %0, %1;" : "=f"(y) : "f"(x)); return y;
}
__device__ __forceinline__ unsigned cvt_bf2(float lo, float hi) {
    unsigned d; asm("cvt.rn.bf16x2.f32 %0, %1, %2;" : "=r"(d) : "f"(hi), "f"(lo)); return d;
}
__device__ __forceinline__ uint32_t smem_u32(const void* p) {
    return (uint32_t)__cvta_generic_to_shared(p);
}
__device__ __forceinline__ void cp_async16(uint32_t dst, const void* src) {
    asm volatile("cp.async.cg.shared.global [%0], [%1], 16;" :: "r"(dst), "l"(src));
}
__device__ __forceinline__ void cp_commit() {
    asm volatile("cp.async.commit_group;");
}
__device__ __forceinline__ void ldsm_x4(unsigned r[4], uint32_t addr) {
    asm volatile("ldmatrix.sync.aligned.m8n8.x4.shared.b16 {%0,%1,%2,%3}, [%4];"
        : "=r"(r[0]), "=r"(r[1]), "=r"(r[2]), "=r"(r[3]) : "r"(addr));
}
__device__ __forceinline__ void ldsm_x2(unsigned& r0, unsigned& r1, uint32_t addr) {
    asm volatile("ldmatrix.sync.aligned.m8n8.x2.shared.b16 {%0,%1}, [%2];"
        : "=r"(r0), "=r"(r1) : "r"(addr));
}
__device__ __forceinline__ void mma_bf16(float c[4], const unsigned a[4], const unsigned b[2]) {
    asm volatile("mma.sync.aligned.m16n8k16.row.col.f32.bf16.bf16.f32 "
        "{%0,%1,%2,%3}, {%4,%5,%6,%7}, {%8,%9}, {%0,%1,%2,%3};"
        : "+f"(c[0]), "+f"(c[1]), "+f"(c[2]), "+f"(c[3])
        : "r"(a[0]), "r"(a[1]), "r"(a[2]), "r"(a[3]), "r"(b[0]), "r"(b[1]));
}
// raw fp32 operands (hardware truncates to tf32)
__device__ __forceinline__ void mma_tf32(float c[4],
    float a0, float a1, float a2, float a3, float b0, float b1) {
    asm volatile("mma.sync.aligned.m16n8k8.row.col.f32.tf32.tf32.f32 "
        "{%0,%1,%2,%3}, {%4,%5,%6,%7}, {%8,%9}, {%0,%1,%2,%3};"
        : "+f"(c[0]), "+f"(c[1]), "+f"(c[2]), "+f"(c[3])
        : "r"(__float_as_uint(a0)), "r"(__float_as_uint(a1)),
          "r"(__float_as_uint(a2)), "r"(__float_as_uint(a3)),
          "r"(__float_as_uint(b0)), "r"(__float_as_uint(b1)));
}

// ============================================================================
// Kernel A: tf32 MMA GEMM, one-shot full-K staging.
// Block = 16 rows (one m16 tile) x 32 b, 128 threads; warp = one n8 tile.
// W slice (16 rows x 2KB = 32KB CONTIGUOUS) + lm (64KB contiguous) loaded in
// a single cp.async burst -> one barrier -> full-K MMA from smem.
// 99KB smem -> 2 blocks/SM; grid 528; W stream is pure sequential DRAM.
// ============================================================================
#define GR      16
#define PITCH   516
#define GEMM_SMEM ((B_DIM * PITCH + GR * PITCH) * 4)   // 99072 B

__global__ void __launch_bounds__(128) gemm_tc_kernel(
    const float* __restrict__ Wk, const float* __restrict__ bk,
    const float* __restrict__ Wg, const float* __restrict__ bg,
    const float* __restrict__ lm)
{
    extern __shared__ float smem[];
    float* Bt = smem;                       // lm [32][516]
    float* Wt = smem + B_DIM * PITCH;       // W  [16][516]

    const int tid  = threadIdx.x;
    const int warp = tid >> 5;    // n-tile 0..3
    const int lane = tid & 31;
    const int g    = lane >> 2;   // 0..7
    const int t4   = lane & 3;    // 0..3

    const bool is_k = (blockIdx.x < (K_DIM * H_DIM) / GR);    // first 512 blocks
    const float* W    = is_k ? Wk : Wg;
    const float* bias = is_k ? bk : bg;
    const int rowbase = (is_k ? blockIdx.x : (blockIdx.x - (K_DIM * H_DIM) / GR)) * GR;

    const uint32_t bt_base = smem_u32(Bt);
    const uint32_t wt_base = smem_u32(Wt);

    // lm -> Bt[b][k]: 4096 float4, consecutive tid = consecutive 16B (stream)
    #pragma unroll
    for (int i = 0; i < 32; i++) {
        int s = tid + 128 * i;
        int bb = s >> 7, k4 = (s & 127) * 4;
        cp_async16(bt_base + (uint32_t)(bb * PITCH + k4) * 4,
                   lm + (size_t)bb * L_DIM + k4);
    }
    // W -> Wt[row][k]: 2048 float4, contiguous 32KB region (stream)
    #pragma unroll
    for (int i = 0; i < 16; i++) {
        int s = tid + 128 * i;
        int row = s >> 7, k4 = (s & 127) * 4;
        cp_async16(wt_base + (uint32_t)(row * PITCH + k4) * 4,
                   W + (size_t)(rowbase + row) * L_DIM + k4);
    }
    cp_commit();
    asm volatile("cp.async.wait_group 0;");
    __syncthreads();

    // full-K accumulation; two accumulators break the MMA dependency chain
    float c0[4] = {0.f, 0.f, 0.f, 0.f};
    float c1[4] = {0.f, 0.f, 0.f, 0.f};
    const float* arow = Wt + g * PITCH + t4;
    const float* brow = Bt + (warp * 8 + g) * PITCH + t4;

    #pragma unroll 4
    for (int ks = 0; ks < L_DIM / 8; ks++) {            // 64 k-steps of 8
        const float* ar = arow + ks * 8;
        float a0 = ar[0], a1 = ar[8 * PITCH], a2 = ar[4], a3 = ar[8 * PITCH + 4];
        const float* br = brow + ks * 8;
        float b0 = br[0], b1 = br[4];
        if (ks & 1) mma_tf32(c1, a0, a1, a2, a3, b0, b1);
        else        mma_tf32(c0, a0, a1, a2, a3, b0, b1);
    }
    #pragma unroll
    for (int j = 0; j < 4; j++) c0[j] += c1[j];

    // epilogue: c0[0,1] -> (row g, b 2t4/2t4+1), c0[2,3] -> (row g+8, ...)
    const int row0 = rowbase + g;
    const float bv0 = bias[row0];
    const float bv1 = bias[row0 + 8];
    const int bb = warp * 8 + 2 * t4;
    if (is_k) {
        float* o0 = g_kern + (size_t)bb * (H_DIM * K_DIM);
        o0[row0]                     = c0[0] + bv0;
        o0[row0 + H_DIM * K_DIM]     = c0[1] + bv0;   // bb+1
        o0[row0 + 8]                 = c0[2] + bv1;
        o0[row0 + 8 + H_DIM * K_DIM] = c0[3] + bv1;
    } else {
        float* o0 = g_glob + (size_t)bb * H_DIM;
        o0[row0]             = c0[0] + bv0;
        o0[row0 + H_DIM]     = c0[1] + bv0;
        o0[row0 + 8]         = c0[2] + bv1;
        o0[row0 + 8 + H_DIM] = c0[3] + bv1;
    }
}

// ============================================================================
// Kernel B: tensor-core conv + enc + global -> tanh -> Ws -> exp
// enc staged through smem (cp.async double buffer) — frozen R7 version
// ============================================================================
#define EPITCH 260
#define SC_SMEM ((2 * 16 * EPITCH + 2560 + 5120 + 160 + 512 + 4 + 4) * 4)

__global__ void __launch_bounds__(128) score_kernel(
    const float* __restrict__ enc,   // (T,B,H)
    const float* __restrict__ prev,  // (T,B)
    const float* __restrict__ mask,  // (T,B)
    const float* __restrict__ Ws,    // (H)
    const float* __restrict__ bsp)   // (1)
{
    extern __shared__ float dsm[];
    float*    E_sm  = dsm;                                      // [2][16][260]
    unsigned* A_sm  = reinterpret_cast<unsigned*>(dsm + 2 * 16 * EPITCH);
    unsigned* B_sm  = A_sm + 2560;                              // 256*20
    float*    win_s = reinterpret_cast<float*>(B_sm + 5120);    // 160
    float*    part  = win_s + 160;                              // [128][4]
    float*    red4  = part + 512;                               // 4

    const int b    = blockIdx.y;
    const int t0   = blockIdx.x * T_BLK;
    const int tid  = threadIdx.x;
    const int wid  = tid >> 5;
    const int lane = tid & 31;
    const int gid  = lane >> 2;
    const int tig  = lane & 3;

    const uint32_t e_base = smem_u32(E_sm);

    // stage enc m=0 (group 0)
    #pragma unroll
    for (int i = 0; i < 8; i++) {
        int s = tid + 128 * i;
        int r = s >> 6, c16 = (s & 63) * 4;
        cp_async16(e_base + (uint32_t)(r * EPITCH + c16) * 4,
                   enc + ((size_t)(t0 + r) * B_DIM + b) * H_DIM + c16);
    }
    cp_commit();

    for (int i = tid; i < 160; i += 128) {
        int tg = t0 + i - (K_DIM - 1);
        win_s[i] = (tg >= 0 && tg < T_DIM) ? prev[(size_t)tg * B_DIM + b] : 0.f;
    }
    {
        const float2* kp = reinterpret_cast<const float2*>(g_kern + (size_t)b * H_DIM * K_DIM);
        #pragma unroll
        for (int i = tid; i < (H_DIM * K_DIM) / 2; i += 128) {
            float2 v = kp[i];
            int h = i >> 4, k2 = i & 15;
            B_sm[h * 20 + k2] = cvt_bf2(v.x, v.y);
        }
    }
    __syncthreads();

    {
        int r = tid;
        #pragma unroll
        for (int k2 = 0; k2 < 16; k2++)
            A_sm[r * 20 + k2] = cvt_bf2(win_s[r + 2 * k2], win_s[r + 2 * k2 + 1]);
    }

    const int hw0 = wid * 64;
    unsigned Bf[8][2][2];
    {
        uint32_t bbase = smem_u32(B_sm);
        #pragma unroll
        for (int j = 0; j < 8; j++)
            #pragma unroll
            for (int kt = 0; kt < 2; kt++) {
                uint32_t addr = bbase + (uint32_t)(hw0 + j * 8 + (lane & 7)) * 80
                              + kt * 32 + ((lane >> 3) & 1) * 16;
                ldsm_x2(Bf[j][kt][0], Bf[j][kt][1], addr);
            }
    }
    float2 gv2[8], ws2[8];
    #pragma unroll
    for (int j = 0; j < 8; j++) {
        int h0 = hw0 + j * 8 + 2 * tig;
        gv2[j] = *reinterpret_cast<const float2*>(g_glob + (size_t)b * H_DIM + h0);
        ws2[j] = *reinterpret_cast<const float2*>(Ws + h0);
    }
    __syncthreads();

    const uint32_t abase = smem_u32(A_sm);
    const uint32_t a_off = (uint32_t)(lane & 15) * 80 + (uint32_t)(lane >> 4) * 16;

    #pragma unroll 1
    for (int m = 0; m < 8; m++) {
        asm volatile("cp.async.wait_group 0;");
        __syncthreads();

        if (m + 1 < 8) {
            uint32_t dst = e_base + (uint32_t)(((m + 1) & 1) * 16 * EPITCH) * 4;
            #pragma unroll
            for (int i = 0; i < 8; i++) {
                int s = tid + 128 * i;
                int r = s >> 6, c16 = (s & 63) * 4;
                cp_async16(dst + (uint32_t)(r * EPITCH + c16) * 4,
                           enc + ((size_t)(t0 + (m + 1) * 16 + r) * B_DIM + b) * H_DIM + c16);
            }
        }
        cp_commit();

        unsigned a0[4], a1[4];
        ldsm_x4(a0, abase + (uint32_t)m * 16 * 80 + a_off);
        ldsm_x4(a1, abase + (uint32_t)m * 16 * 80 + a_off + 32);

        const float* E = E_sm + (m & 1) * 16 * EPITCH;

        float sum0 = 0.f, sum1 = 0.f;
        #pragma unroll
        for (int jh = 0; jh < 2; jh++) {
            float c[4][4];
            #pragma unroll
            for (int j4 = 0; j4 < 4; j4++) {
                c[j4][0] = c[j4][1] = c[j4][2] = c[j4][3] = 0.f;
                mma_bf16(c[j4], a0, Bf[jh * 4 + j4][0]);
                mma_bf16(c[j4], a1, Bf[jh * 4 + j4][1]);
            }
            #pragma unroll
            for (int j4 = 0; j4 < 4; j4++) {
                int j = jh * 4 + j4;
                int h0 = hw0 + j * 8 + 2 * tig;
                float2 e0 = *reinterpret_cast<const float2*>(E + gid * EPITCH + h0);
                float2 e1 = *reinterpret_cast<const float2*>(E + (gid + 8) * EPITCH + h0);
                sum0 += ws2[j].x * tanh_ap(c[j4][0] + e0.x + gv2[j].x)
                      + ws2[j].y * tanh_ap(c[j4][1] + e0.y + gv2[j].y);
                sum1 += ws2[j].x * tanh_ap(c[j4][2] + e1.x + gv2[j].x)
                      + ws2[j].y * tanh_ap(c[j4][3] + e1.y + gv2[j].y);
            }
        }
        sum0 += __shfl_xor_sync(0xFFFFFFFFu, sum0, 1);
        sum0 += __shfl_xor_sync(0xFFFFFFFFu, sum0, 2);
        sum1 += __shfl_xor_sync(0xFFFFFFFFu, sum1, 1);
        sum1 += __shfl_xor_sync(0xFFFFFFFFu, sum1, 2);
        if (tig == 0) {
            part[(m * 16 + gid) * 4 + wid]     = sum0;
            part[(m * 16 + gid + 8) * 4 + wid] = sum1;
        }
    }
    __syncthreads();

    const int t = t0 + tid;
    float s = part[tid * 4 + 0] + part[tid * 4 + 1] + part[tid * 4 + 2] + part[tid * 4 + 3]
            + bsp[0];
    float e = __expf(s + mask[(size_t)t * B_DIM + b]);
    g_exp[(size_t)t * B_DIM + b] = e;

    float v = e;
    v += __shfl_xor_sync(0xFFFFFFFFu, v, 16);
    v += __shfl_xor_sync(0xFFFFFFFFu, v, 8);
    v += __shfl_xor_sync(0xFFFFFFFFu, v, 4);
    v += __shfl_xor_sync(0xFFFFFFFFu, v, 2);
    v += __shfl_xor_sync(0xFFFFFFFFu, v, 1);
    if (lane == 0) red4[wid] = v;
    __syncthreads();
    if (tid == 0)
        g_part[(size_t)blockIdx.x * B_DIM + b] = red4[0] + red4[1] + red4[2] + red4[3];
}

// ============================================================================
// Kernel C: normalize
// ============================================================================
__global__ void __launch_bounds__(128) norm_kernel(float* __restrict__ out)
{
    __shared__ float inv_s;
    const int b = blockIdx.y;
    const int tid = threadIdx.x;

    if (tid < 32) {
        float v = g_part[(size_t)tid * B_DIM + b];
        v += __shfl_xor_sync(0xFFFFFFFFu, v, 16);
        v += __shfl_xor_sync(0xFFFFFFFFu, v, 8);
        v += __shfl_xor_sync(0xFFFFFFFFu, v, 4);
        v += __shfl_xor_sync(0xFFFFFFFFu, v, 2);
        v += __shfl_xor_sync(0xFFFFFFFFu, v, 1);
        if (tid == 0) inv_s = 1.0f / v;
    }
    __syncthreads();

    int t = blockIdx.x * 128 + tid;
    out[(size_t)t * B_DIM + b] = g_exp[(size_t)t * B_DIM + b] * inv_s;
}

// ============================================================================
extern "C" void kernel_launch(void* const* d_in, const int* in_sizes, int n_in,
                              void* d_out, int out_size)
{
    const float* enc  = (const float*)d_in[0];
    const float* mask = (const float*)d_in[1];
    const float* lm   = (const float*)d_in[2];
    const float* prev = (const float*)d_in[3];
    const float* Wk   = (const float*)d_in[4];
    const float* bk   = (const float*)d_in[5];
    const float* Wg   = (const float*)d_in[6];
    const float* bg   = (const float*)d_in[7];
    const float* Ws   = (const float*)d_in[8];
    const float* bs   = (const float*)d_in[9];
    float* out = (float*)d_out;

    static bool attr_set = false;
    if (!attr_set) {
        cudaFuncSetAttribute(gemm_tc_kernel,
                             cudaFuncAttributeMaxDynamicSharedMemorySize, GEMM_SMEM);
        cudaFuncSetAttribute(score_kernel,
                             cudaFuncAttributeMaxDynamicSharedMemorySize, SC_SMEM);
        attr_set = true;
    }

    // Wk (512 blocks) + Wg (16 blocks), one-shot streaming tf32 GEMM
    gemm_tc_kernel<<<(K_DIM * H_DIM) / GR + H_DIM / GR, 128, GEMM_SMEM>>>(
        Wk, bk, Wg, bg, lm);
    score_kernel<<<dim3(T_DIM / T_BLK, B_DIM), 128, SC_SMEM>>>(enc, prev, mask, Ws, bs);
    norm_kernel<<<dim3(T_DIM / 128, B_DIM), 128>>>(out);
}

// round 10
// speedup vs baseline: 1.0351x; 1.0351x over previous
#include <cuda_runtime.h>
#include <cstdint>

#define T_DIM 4096
#define B_DIM 32
#define H_DIM 256
#define L_DIM 512
#define K_DIM 32
#define T_BLK 128

// Scratch (allocation-free contract: __device__ globals)
__device__ __align__(16) float g_kern[B_DIM * H_DIM * K_DIM];   // [b][h*K+k] fp32
__device__ __align__(16) float g_glob[B_DIM * H_DIM];           // (B,H)
__device__ __align__(16) float g_exp[T_DIM * B_DIM];            // exp(score+mask)
__device__ __align__(16) float g_part[(T_DIM / T_BLK) * B_DIM]; // partial exp sums

// ---- helpers ----
__device__ __forceinline__ float tanh_ap(float x) {
    float y; asm("tanh.approx.f32 %0, %1;" : "=f"(y) : "f"(x)); return y;
}
__device__ __forceinline__ unsigned cvt_bf2(float lo, float hi) {
    unsigned d; asm("cvt.rn.bf16x2.f32 %0, %1, %2;" : "=r"(d) : "f"(hi), "f"(lo)); return d;
}
__device__ __forceinline__ uint32_t smem_u32(const void* p) {
    return (uint32_t)__cvta_generic_to_shared(p);
}
// ---- mbarrier + TMA bulk ----
__device__ __forceinline__ void mbar_init(uint32_t addr, uint32_t count) {
    asm volatile("mbarrier.init.shared.b64 [%0], %1;" :: "r"(addr), "r"(count) : "memory");
}
__device__ __forceinline__ void mbar_expect_tx(uint32_t addr, uint32_t bytes) {
    asm volatile("mbarrier.arrive.expect_tx.shared.b64 _, [%0], %1;"
        :: "r"(addr), "r"(bytes) : "memory");
}
__device__ __forceinline__ void mbar_wait(uint32_t addr, uint32_t parity) {
    asm volatile(
        "{\n\t"
        ".reg .pred P;\n"
        "WAIT_%=:\n\t"
        "mbarrier.try_wait.parity.shared.b64 P, [%0], %1;\n\t"
        "@!P bra WAIT_%=;\n\t"
        "}"
        :: "r"(addr), "r"(parity) : "memory");
}
__device__ __forceinline__ void bulk_g2s(uint32_t dst, const void* src,
                                         uint32_t bytes, uint32_t mbar) {
    asm volatile(
        "cp.async.bulk.shared::cta.global.mbarrier::complete_tx::bytes [%0], [%1], %2, [%3];"
        :: "r"(dst), "l"(src), "r"(bytes), "r"(mbar) : "memory");
}
__device__ __forceinline__ void ldsm_x4(unsigned r[4], uint32_t addr) {
    asm volatile("ldmatrix.sync.aligned.m8n8.x4.shared.b16 {%0,%1,%2,%3}, [%4];"
        : "=r"(r[0]), "=r"(r[1]), "=r"(r[2]), "=r"(r[3]) : "r"(addr));
}
__device__ __forceinline__ void ldsm_x2(unsigned& r0, unsigned& r1, uint32_t addr) {
    asm volatile("ldmatrix.sync.aligned.m8n8.x2.shared.b16 {%0,%1}, [%2];"
        : "=r"(r0), "=r"(r1) : "r"(addr));
}
__device__ __forceinline__ void mma_bf16(float c[4], const unsigned a[4], const unsigned b[2]) {
    asm volatile("mma.sync.aligned.m16n8k16.row.col.f32.bf16.bf16.f32 "
        "{%0,%1,%2,%3}, {%4,%5,%6,%7}, {%8,%9}, {%0,%1,%2,%3};"
        : "+f"(c[0]), "+f"(c[1]), "+f"(c[2]), "+f"(c[3])
        : "r"(a[0]), "r"(a[1]), "r"(a[2]), "r"(a[3]), "r"(b[0]), "r"(b[1]));
}
// raw fp32 operands (hardware truncates to tf32)
__device__ __forceinline__ void mma_tf32(float c[4],
    float a0, float a1, float a2, float a3, float b0, float b1) {
    asm volatile("mma.sync.aligned.m16n8k8.row.col.f32.tf32.tf32.f32 "
        "{%0,%1,%2,%3}, {%4,%5,%6,%7}, {%8,%9}, {%0,%1,%2,%3};"
        : "+f"(c[0]), "+f"(c[1]), "+f"(c[2]), "+f"(c[3])
        : "r"(__float_as_uint(a0)), "r"(__float_as_uint(a1)),
          "r"(__float_as_uint(a2)), "r"(__float_as_uint(a3)),
          "r"(__float_as_uint(b0)), "r"(__float_as_uint(b1)));
}

// ============================================================================
// Kernel A: tf32 MMA GEMM. W + lm staged via 48 TMA bulk row-copies
// (one mbarrier), eliminating the LDGSTS issue-rate bottleneck.
// Block = 16 rows x 32 b, 128 threads; 2 blocks/SM; grid 528.
// ============================================================================
#define GR      16
#define PITCH   516
#define GEMM_SMEM (((B_DIM + GR) * PITCH) * 4 + 16)

__global__ void __launch_bounds__(128) gemm_tc_kernel(
    const float* __restrict__ Wk, const float* __restrict__ bk,
    const float* __restrict__ Wg, const float* __restrict__ bg,
    const float* __restrict__ lm)
{
    extern __shared__ float smem[];
    float* Bt = smem;                       // lm [32][516]
    float* Wt = smem + B_DIM * PITCH;       // W  [16][516]
    const uint32_t mbar = smem_u32(smem + (B_DIM + GR) * PITCH);

    const int tid  = threadIdx.x;
    const int warp = tid >> 5;    // n-tile 0..3
    const int lane = tid & 31;
    const int g    = lane >> 2;   // 0..7
    const int t4   = lane & 3;    // 0..3

    const bool is_k = (blockIdx.x < (K_DIM * H_DIM) / GR);    // first 512 blocks
    const float* W    = is_k ? Wk : Wg;
    const float* bias = is_k ? bk : bg;
    const int rowbase = (is_k ? blockIdx.x : (blockIdx.x - (K_DIM * H_DIM) / GR)) * GR;

    const uint32_t bt_base = smem_u32(Bt);
    const uint32_t wt_base = smem_u32(Wt);

    if (tid == 0) mbar_init(mbar, 1);
    __syncthreads();
    if (tid == 0) {
        mbar_expect_tx(mbar, (GR + B_DIM) * L_DIM * 4);
        #pragma unroll
        for (int r = 0; r < GR; r++)
            bulk_g2s(wt_base + (uint32_t)(r * PITCH) * 4,
                     W + (size_t)(rowbase + r) * L_DIM, L_DIM * 4, mbar);
        #pragma unroll
        for (int bb = 0; bb < B_DIM; bb++)
            bulk_g2s(bt_base + (uint32_t)(bb * PITCH) * 4,
                     lm + (size_t)bb * L_DIM, L_DIM * 4, mbar);
    }
    mbar_wait(mbar, 0);

    // full-K accumulation; two accumulators break the MMA dependency chain
    float c0[4] = {0.f, 0.f, 0.f, 0.f};
    float c1[4] = {0.f, 0.f, 0.f, 0.f};
    const float* arow = Wt + g * PITCH + t4;
    const float* brow = Bt + (warp * 8 + g) * PITCH + t4;

    #pragma unroll 4
    for (int ks = 0; ks < L_DIM / 8; ks++) {            // 64 k-steps of 8
        const float* ar = arow + ks * 8;
        float a0 = ar[0], a1 = ar[8 * PITCH], a2 = ar[4], a3 = ar[8 * PITCH + 4];
        const float* br = brow + ks * 8;
        float b0 = br[0], b1 = br[4];
        if (ks & 1) mma_tf32(c1, a0, a1, a2, a3, b0, b1);
        else        mma_tf32(c0, a0, a1, a2, a3, b0, b1);
    }
    #pragma unroll
    for (int j = 0; j < 4; j++) c0[j] += c1[j];

    const int row0 = rowbase + g;
    const float bv0 = bias[row0];
    const float bv1 = bias[row0 + 8];
    const int bb = warp * 8 + 2 * t4;
    if (is_k) {
        float* o0 = g_kern + (size_t)bb * (H_DIM * K_DIM);
        o0[row0]                     = c0[0] + bv0;
        o0[row0 + H_DIM * K_DIM]     = c0[1] + bv0;   // bb+1
        o0[row0 + 8]                 = c0[2] + bv1;
        o0[row0 + 8 + H_DIM * K_DIM] = c0[3] + bv1;
    } else {
        float* o0 = g_glob + (size_t)bb * H_DIM;
        o0[row0]             = c0[0] + bv0;
        o0[row0 + H_DIM]     = c0[1] + bv0;
        o0[row0 + 8]         = c0[2] + bv1;
        o0[row0 + 8 + H_DIM] = c0[3] + bv1;
    }
}

// ============================================================================
// Kernel B: tensor-core conv + enc + global -> tanh -> Ws -> exp
// enc staged via TMA bulk copies (16 x 1KB rows per m-iter), double-buffered
// with two mbarriers. 16 bulk instrs replace 1024 LDGSTS per iteration.
// ============================================================================
#define EPITCH 260
#define SC_FLOATS (2 * 16 * EPITCH + 2560 + 5120 + 160 + 512 + 4)
#define SC_SMEM (SC_FLOATS * 4 + 32)

__global__ void __launch_bounds__(128) score_kernel(
    const float* __restrict__ enc,   // (T,B,H)
    const float* __restrict__ prev,  // (T,B)
    const float* __restrict__ mask,  // (T,B)
    const float* __restrict__ Ws,    // (H)
    const float* __restrict__ bsp)   // (1)
{
    extern __shared__ float dsm[];
    float*    E_sm  = dsm;                                      // [2][16][260]
    unsigned* A_sm  = reinterpret_cast<unsigned*>(dsm + 2 * 16 * EPITCH);
    unsigned* B_sm  = A_sm + 2560;                              // 256*20
    float*    win_s = reinterpret_cast<float*>(B_sm + 5120);    // 160
    float*    part  = win_s + 160;                              // [128][4]
    float*    red4  = part + 512;                               // 4
    const uint32_t mb0 = smem_u32(dsm + SC_FLOATS);
    const uint32_t mb1 = mb0 + 8;

    const int b    = blockIdx.y;
    const int t0   = blockIdx.x * T_BLK;
    const int tid  = threadIdx.x;
    const int wid  = tid >> 5;
    const int lane = tid & 31;
    const int gid  = lane >> 2;
    const int tig  = lane & 3;

    const uint32_t e_base = smem_u32(E_sm);

    if (tid == 0) { mbar_init(mb0, 1); mbar_init(mb1, 1); }
    __syncthreads();

    // stage enc m=0 into buffer 0
    if (tid == 0) {
        mbar_expect_tx(mb0, 16 * H_DIM * 4);
        #pragma unroll
        for (int r = 0; r < 16; r++)
            bulk_g2s(e_base + (uint32_t)(r * EPITCH) * 4,
                     enc + ((size_t)(t0 + r) * B_DIM + b) * H_DIM, H_DIM * 4, mb0);
    }

    for (int i = tid; i < 160; i += 128) {
        int tg = t0 + i - (K_DIM - 1);
        win_s[i] = (tg >= 0 && tg < T_DIM) ? prev[(size_t)tg * B_DIM + b] : 0.f;
    }
    {
        const float2* kp = reinterpret_cast<const float2*>(g_kern + (size_t)b * H_DIM * K_DIM);
        #pragma unroll
        for (int i = tid; i < (H_DIM * K_DIM) / 2; i += 128) {
            float2 v = kp[i];
            int h = i >> 4, k2 = i & 15;
            B_sm[h * 20 + k2] = cvt_bf2(v.x, v.y);
        }
    }
    __syncthreads();

    {
        int r = tid;
        #pragma unroll
        for (int k2 = 0; k2 < 16; k2++)
            A_sm[r * 20 + k2] = cvt_bf2(win_s[r + 2 * k2], win_s[r + 2 * k2 + 1]);
    }

    const int hw0 = wid * 64;
    unsigned Bf[8][2][2];
    {
        uint32_t bbase = smem_u32(B_sm);
        #pragma unroll
        for (int j = 0; j < 8; j++)
            #pragma unroll
            for (int kt = 0; kt < 2; kt++) {
                uint32_t addr = bbase + (uint32_t)(hw0 + j * 8 + (lane & 7)) * 80
                              + kt * 32 + ((lane >> 3) & 1) * 16;
                ldsm_x2(Bf[j][kt][0], Bf[j][kt][1], addr);
            }
    }
    float2 gv2[8], ws2[8];
    #pragma unroll
    for (int j = 0; j < 8; j++) {
        int h0 = hw0 + j * 8 + 2 * tig;
        gv2[j] = *reinterpret_cast<const float2*>(g_glob + (size_t)b * H_DIM + h0);
        ws2[j] = *reinterpret_cast<const float2*>(Ws + h0);
    }
    __syncthreads();

    const uint32_t abase = smem_u32(A_sm);
    const uint32_t a_off = (uint32_t)(lane & 15) * 80 + (uint32_t)(lane >> 4) * 16;

    #pragma unroll 1
    for (int m = 0; m < 8; m++) {
        // wait for this m's enc tile; parity = use-index parity of that mbar
        mbar_wait((m & 1) ? mb1 : mb0, (m >> 1) & 1);
        __syncthreads();   // all warps done with the OTHER buffer -> safe to refill

        if (m + 1 < 8 && tid == 0) {
            uint32_t mb = ((m + 1) & 1) ? mb1 : mb0;
            mbar_expect_tx(mb, 16 * H_DIM * 4);
            uint32_t dst = e_base + (uint32_t)(((m + 1) & 1) * 16 * EPITCH) * 4;
            #pragma unroll
            for (int r = 0; r < 16; r++)
                bulk_g2s(dst + (uint32_t)(r * EPITCH) * 4,
                         enc + ((size_t)(t0 + (m + 1) * 16 + r) * B_DIM + b) * H_DIM,
                         H_DIM * 4, mb);
        }

        unsigned a0[4], a1[4];
        ldsm_x4(a0, abase + (uint32_t)m * 16 * 80 + a_off);
        ldsm_x4(a1, abase + (uint32_t)m * 16 * 80 + a_off + 32);

        const float* E = E_sm + (m & 1) * 16 * EPITCH;

        float sum0 = 0.f, sum1 = 0.f;
        #pragma unroll
        for (int jh = 0; jh < 2; jh++) {
            float c[4][4];
            #pragma unroll
            for (int j4 = 0; j4 < 4; j4++) {
                c[j4][0] = c[j4][1] = c[j4][2] = c[j4][3] = 0.f;
                mma_bf16(c[j4], a0, Bf[jh * 4 + j4][0]);
                mma_bf16(c[j4], a1, Bf[jh * 4 + j4][1]);
            }
            #pragma unroll
            for (int j4 = 0; j4 < 4; j4++) {
                int j = jh * 4 + j4;
                int h0 = hw0 + j * 8 + 2 * tig;
                float2 e0 = *reinterpret_cast<const float2*>(E + gid * EPITCH + h0);
                float2 e1 = *reinterpret_cast<const float2*>(E + (gid + 8) * EPITCH + h0);
                sum0 += ws2[j].x * tanh_ap(c[j4][0] + e0.x + gv2[j].x)
                      + ws2[j].y * tanh_ap(c[j4][1] + e0.y + gv2[j].y);
                sum1 += ws2[j].x * tanh_ap(c[j4][2] + e1.x + gv2[j].x)
                      + ws2[j].y * tanh_ap(c[j4][3] + e1.y + gv2[j].y);
            }
        }
        sum0 += __shfl_xor_sync(0xFFFFFFFFu, sum0, 1);
        sum0 += __shfl_xor_sync(0xFFFFFFFFu, sum0, 2);
        sum1 += __shfl_xor_sync(0xFFFFFFFFu, sum1, 1);
        sum1 += __shfl_xor_sync(0xFFFFFFFFu, sum1, 2);
        if (tig == 0) {
            part[(m * 16 + gid) * 4 + wid]     = sum0;
            part[(m * 16 + gid + 8) * 4 + wid] = sum1;
        }
    }
    __syncthreads();

    const int t = t0 + tid;
    float s = part[tid * 4 + 0] + part[tid * 4 + 1] + part[tid * 4 + 2] + part[tid * 4 + 3]
            + bsp[0];
    float e = __expf(s + mask[(size_t)t * B_DIM + b]);
    g_exp[(size_t)t * B_DIM + b] = e;

    float v = e;
    v += __shfl_xor_sync(0xFFFFFFFFu, v, 16);
    v += __shfl_xor_sync(0xFFFFFFFFu, v, 8);
    v += __shfl_xor_sync(0xFFFFFFFFu, v, 4);
    v += __shfl_xor_sync(0xFFFFFFFFu, v, 2);
    v += __shfl_xor_sync(0xFFFFFFFFu, v, 1);
    if (lane == 0) red4[wid] = v;
    __syncthreads();
    if (tid == 0)
        g_part[(size_t)blockIdx.x * B_DIM + b] = red4[0] + red4[1] + red4[2] + red4[3];
}

// ============================================================================
// Kernel C: normalize
// ============================================================================
__global__ void __launch_bounds__(128) norm_kernel(float* __restrict__ out)
{
    __shared__ float inv_s;
    const int b = blockIdx.y;
    const int tid = threadIdx.x;

    if (tid < 32) {
        float v = g_part[(size_t)tid * B_DIM + b];
        v += __shfl_xor_sync(0xFFFFFFFFu, v, 16);
        v += __shfl_xor_sync(0xFFFFFFFFu, v, 8);
        v += __shfl_xor_sync(0xFFFFFFFFu, v, 4);
        v += __shfl_xor_sync(0xFFFFFFFFu, v, 2);
        v += __shfl_xor_sync(0xFFFFFFFFu, v, 1);
        if (tid == 0) inv_s = 1.0f / v;
    }
    __syncthreads();

    int t = blockIdx.x * 128 + tid;
    out[(size_t)t * B_DIM + b] = g_exp[(size_t)t * B_DIM + b] * inv_s;
}

// ============================================================================
extern "C" void kernel_launch(void* const* d_in, const int* in_sizes, int n_in,
                              void* d_out, int out_size)
{
    const float* enc  = (const float*)d_in[0];
    const float* mask = (const float*)d_in[1];
    const float* lm   = (const float*)d_in[2];
    const float* prev = (const float*)d_in[3];
    const float* Wk   = (const float*)d_in[4];
    const float* bk   = (const float*)d_in[5];
    const float* Wg   = (const float*)d_in[6];
    const float* bg   = (const float*)d_in[7];
    const float* Ws   = (const float*)d_in[8];
    const float* bs   = (const float*)d_in[9];
    float* out = (float*)d_out;

    static bool attr_set = false;
    if (!attr_set) {
        cudaFuncSetAttribute(gemm_tc_kernel,
                             cudaFuncAttributeMaxDynamicSharedMemorySize, GEMM_SMEM);
        cudaFuncSetAttribute(score_kernel,
                             cudaFuncAttributeMaxDynamicSharedMemorySize, SC_SMEM);
        attr_set = true;
    }

    // Wk (512 blocks) + Wg (16 blocks), TMA-bulk streaming tf32 GEMM
    gemm_tc_kernel<<<(K_DIM * H_DIM) / GR + H_DIM / GR, 128, GEMM_SMEM>>>(
        Wk, bk, Wg, bg, lm);
    score_kernel<<<dim3(T_DIM / T_BLK, B_DIM), 128, SC_SMEM>>>(enc, prev, mask, Ws, bs);
    norm_kernel<<<dim3(T_DIM / 128, B_DIM), 128>>>(out);
}

// round 11
// speedup vs baseline: 1.0357x; 1.0006x over previous
#include <cuda_runtime.h>
#include <cstdint>

#define T_DIM 4096
#define B_DIM 32
#define H_DIM 256
#define L_DIM 512
#define K_DIM 32
#define T_BLK 128

// Scratch (allocation-free contract: __device__ globals)
__device__ __align__(16) float g_kern[B_DIM * H_DIM * K_DIM];   // [b][h*K+k] fp32
__device__ __align__(16) float g_glob[B_DIM * H_DIM];           // (B,H)
__device__ __align__(16) float g_exp[T_DIM * B_DIM];            // exp(score+mask)
__device__ __align__(16) float g_part[(T_DIM / T_BLK) * B_DIM]; // partial exp sums

// ---- helpers ----
__device__ __forceinline__ float tanh_ap(float x) {
    float y; asm("tanh.approx.f32 %0, %1;" : "=f"(y) : "f"(x)); return y;
}
__device__ __forceinline__ unsigned cvt_bf2(float lo, float hi) {
    unsigned d; asm("cvt.rn.bf16x2.f32 %0, %1, %2;" : "=r"(d) : "f"(hi), "f"(lo)); return d;
}
__device__ __forceinline__ uint32_t smem_u32(const void* p) {
    return (uint32_t)__cvta_generic_to_shared(p);
}
// ---- mbarrier + TMA bulk ----
__device__ __forceinline__ void mbar_init(uint32_t addr, uint32_t count) {
    asm volatile("mbarrier.init.shared.b64 [%0], %1;" :: "r"(addr), "r"(count) : "memory");
}
__device__ __forceinline__ void mbar_expect_tx(uint32_t addr, uint32_t bytes) {
    asm volatile("mbarrier.arrive.expect_tx.shared.b64 _, [%0], %1;"
        :: "r"(addr), "r"(bytes) : "memory");
}
__device__ __forceinline__ void mbar_wait(uint32_t addr, uint32_t parity) {
    asm volatile(
        "{\n\t"
        ".reg .pred P;\n"
        "WAIT_%=:\n\t"
        "mbarrier.try_wait.parity.shared.b64 P, [%0], %1;\n\t"
        "@!P bra WAIT_%=;\n\t"
        "}"
        :: "r"(addr), "r"(parity) : "memory");
}
__device__ __forceinline__ void bulk_g2s(uint32_t dst, const void* src,
                                         uint32_t bytes, uint32_t mbar) {
    asm volatile(
        "cp.async.bulk.shared::cta.global.mbarrier::complete_tx::bytes [%0], [%1], %2, [%3];"
        :: "r"(dst), "l"(src), "r"(bytes), "r"(mbar) : "memory");
}
__device__ __forceinline__ void ldsm_x4(unsigned r[4], uint32_t addr) {
    asm volatile("ldmatrix.sync.aligned.m8n8.x4.shared.b16 {%0,%1,%2,%3}, [%4];"
        : "=r"(r[0]), "=r"(r[1]), "=r"(r[2]), "=r"(r[3]) : "r"(addr));
}
__device__ __forceinline__ void ldsm_x2(unsigned& r0, unsigned& r1, uint32_t addr) {
    asm volatile("ldmatrix.sync.aligned.m8n8.x2.shared.b16 {%0,%1}, [%2];"
        : "=r"(r0), "=r"(r1) : "r"(addr));
}
__device__ __forceinline__ void mma_bf16(float c[4], const unsigned a[4], const unsigned b[2]) {
    asm volatile("mma.sync.aligned.m16n8k16.row.col.f32.bf16.bf16.f32 "
        "{%0,%1,%2,%3}, {%4,%5,%6,%7}, {%8,%9}, {%0,%1,%2,%3};"
        : "+f"(c[0]), "+f"(c[1]), "+f"(c[2]), "+f"(c[3])
        : "r"(a[0]), "r"(a[1]), "r"(a[2]), "r"(a[3]), "r"(b[0]), "r"(b[1]));
}
// raw fp32 operands (hardware truncates to tf32)
__device__ __forceinline__ void mma_tf32(float c[4],
    float a0, float a1, float a2, float a3, float b0, float b1) {
    asm volatile("mma.sync.aligned.m16n8k8.row.col.f32.tf32.tf32.f32 "
        "{%0,%1,%2,%3}, {%4,%5,%6,%7}, {%8,%9}, {%0,%1,%2,%3};"
        : "+f"(c[0]), "+f"(c[1]), "+f"(c[2]), "+f"(c[3])
        : "r"(__float_as_uint(a0)), "r"(__float_as_uint(a1)),
          "r"(__float_as_uint(a2)), "r"(__float_as_uint(a3)),
          "r"(__float_as_uint(b0)), "r"(__float_as_uint(b1)));
}

// ============================================================================
// Kernel A: tf32 MMA GEMM. W + lm staged via 48 TMA bulk row-copies.
// (frozen from R10: 13.2us, DRAM-stream of W)
// ============================================================================
#define GR      16
#define PITCH   516
#define GEMM_SMEM (((B_DIM + GR) * PITCH) * 4 + 16)

__global__ void __launch_bounds__(128) gemm_tc_kernel(
    const float* __restrict__ Wk, const float* __restrict__ bk,
    const float* __restrict__ Wg, const float* __restrict__ bg,
    const float* __restrict__ lm)
{
    extern __shared__ float smem[];
    float* Bt = smem;                       // lm [32][516]
    float* Wt = smem + B_DIM * PITCH;       // W  [16][516]
    const uint32_t mbar = smem_u32(smem + (B_DIM + GR) * PITCH);

    const int tid  = threadIdx.x;
    const int warp = tid >> 5;
    const int lane = tid & 31;
    const int g    = lane >> 2;
    const int t4   = lane & 3;

    const bool is_k = (blockIdx.x < (K_DIM * H_DIM) / GR);
    const float* W    = is_k ? Wk : Wg;
    const float* bias = is_k ? bk : bg;
    const int rowbase = (is_k ? blockIdx.x : (blockIdx.x - (K_DIM * H_DIM) / GR)) * GR;

    const uint32_t bt_base = smem_u32(Bt);
    const uint32_t wt_base = smem_u32(Wt);

    if (tid == 0) mbar_init(mbar, 1);
    __syncthreads();
    if (tid == 0) {
        mbar_expect_tx(mbar, (GR + B_DIM) * L_DIM * 4);
        #pragma unroll
        for (int r = 0; r < GR; r++)
            bulk_g2s(wt_base + (uint32_t)(r * PITCH) * 4,
                     W + (size_t)(rowbase + r) * L_DIM, L_DIM * 4, mbar);
        #pragma unroll
        for (int bb = 0; bb < B_DIM; bb++)
            bulk_g2s(bt_base + (uint32_t)(bb * PITCH) * 4,
                     lm + (size_t)bb * L_DIM, L_DIM * 4, mbar);
    }
    mbar_wait(mbar, 0);

    float c0[4] = {0.f, 0.f, 0.f, 0.f};
    float c1[4] = {0.f, 0.f, 0.f, 0.f};
    const float* arow = Wt + g * PITCH + t4;
    const float* brow = Bt + (warp * 8 + g) * PITCH + t4;

    #pragma unroll 4
    for (int ks = 0; ks < L_DIM / 8; ks++) {
        const float* ar = arow + ks * 8;
        float a0 = ar[0], a1 = ar[8 * PITCH], a2 = ar[4], a3 = ar[8 * PITCH + 4];
        const float* br = brow + ks * 8;
        float b0 = br[0], b1 = br[4];
        if (ks & 1) mma_tf32(c1, a0, a1, a2, a3, b0, b1);
        else        mma_tf32(c0, a0, a1, a2, a3, b0, b1);
    }
    #pragma unroll
    for (int j = 0; j < 4; j++) c0[j] += c1[j];

    const int row0 = rowbase + g;
    const float bv0 = bias[row0];
    const float bv1 = bias[row0 + 8];
    const int bb = warp * 8 + 2 * t4;
    if (is_k) {
        float* o0 = g_kern + (size_t)bb * (H_DIM * K_DIM);
        o0[row0]                     = c0[0] + bv0;
        o0[row0 + H_DIM * K_DIM]     = c0[1] + bv0;
        o0[row0 + 8]                 = c0[2] + bv1;
        o0[row0 + 8 + H_DIM * K_DIM] = c0[3] + bv1;
    } else {
        float* o0 = g_glob + (size_t)bb * H_DIM;
        o0[row0]             = c0[0] + bv0;
        o0[row0 + H_DIM]     = c0[1] + bv0;
        o0[row0 + 8]         = c0[2] + bv1;
        o0[row0 + 8 + H_DIM] = c0[3] + bv1;
    }
}

// ============================================================================
// Kernel B: tensor-core conv + enc + global -> tanh -> Ws -> exp
// 256 threads / 8 warps; each warp owns 32 h (was 64) -> 24 warps/SM
// at 3 blocks/SM, doubling latency hiding for the MUFU/FMA/LDS chains.
// enc staged via TMA bulk, double-buffered.
// ============================================================================
#define EPITCH 260
#define SC_FLOATS (2 * 16 * EPITCH + 2560 + 5120 + 160 + 1024 + 4)
#define SC_SMEM (SC_FLOATS * 4 + 32)

__global__ void __launch_bounds__(256) score_kernel(
    const float* __restrict__ enc,   // (T,B,H)
    const float* __restrict__ prev,  // (T,B)
    const float* __restrict__ mask,  // (T,B)
    const float* __restrict__ Ws,    // (H)
    const float* __restrict__ bsp)   // (1)
{
    extern __shared__ float dsm[];
    float*    E_sm  = dsm;                                      // [2][16][260]
    unsigned* A_sm  = reinterpret_cast<unsigned*>(dsm + 2 * 16 * EPITCH);
    unsigned* B_sm  = A_sm + 2560;                              // 256*20
    float*    win_s = reinterpret_cast<float*>(B_sm + 5120);    // 160
    float*    part  = win_s + 160;                              // [128][8]
    float*    red4  = part + 1024;                              // 4
    const uint32_t mb0 = smem_u32(dsm + SC_FLOATS);
    const uint32_t mb1 = mb0 + 8;

    const int b    = blockIdx.y;
    const int t0   = blockIdx.x * T_BLK;
    const int tid  = threadIdx.x;
    const int wid  = tid >> 5;    // 0..7
    const int lane = tid & 31;
    const int gid  = lane >> 2;
    const int tig  = lane & 3;

    const uint32_t e_base = smem_u32(E_sm);

    if (tid == 0) { mbar_init(mb0, 1); mbar_init(mb1, 1); }
    __syncthreads();

    // stage enc m=0 into buffer 0
    if (tid == 0) {
        mbar_expect_tx(mb0, 16 * H_DIM * 4);
        #pragma unroll
        for (int r = 0; r < 16; r++)
            bulk_g2s(e_base + (uint32_t)(r * EPITCH) * 4,
                     enc + ((size_t)(t0 + r) * B_DIM + b) * H_DIM, H_DIM * 4, mb0);
    }

    for (int i = tid; i < 160; i += 256) {
        int tg = t0 + i - (K_DIM - 1);
        win_s[i] = (tg >= 0 && tg < T_DIM) ? prev[(size_t)tg * B_DIM + b] : 0.f;
    }
    {
        const float2* kp = reinterpret_cast<const float2*>(g_kern + (size_t)b * H_DIM * K_DIM);
        #pragma unroll
        for (int i = tid; i < (H_DIM * K_DIM) / 2; i += 256) {
            float2 v = kp[i];
            int h = i >> 4, k2 = i & 15;
            B_sm[h * 20 + k2] = cvt_bf2(v.x, v.y);
        }
    }
    __syncthreads();

    // fill A (Hankel windows, bf16): threads 0..127 each build one row
    if (tid < 128) {
        int r = tid;
        #pragma unroll
        for (int k2 = 0; k2 < 16; k2++)
            A_sm[r * 20 + k2] = cvt_bf2(win_s[r + 2 * k2], win_s[r + 2 * k2 + 1]);
    }

    // B fragments: warp owns 32 h = 4 n8-tiles
    const int hw0 = wid * 32;
    unsigned Bf[4][2][2];
    {
        uint32_t bbase = smem_u32(B_sm);
        #pragma unroll
        for (int j = 0; j < 4; j++)
            #pragma unroll
            for (int kt = 0; kt < 2; kt++) {
                uint32_t addr = bbase + (uint32_t)(hw0 + j * 8 + (lane & 7)) * 80
                              + kt * 32 + ((lane >> 3) & 1) * 16;
                ldsm_x2(Bf[j][kt][0], Bf[j][kt][1], addr);
            }
    }
    float2 gv2[4], ws2[4];
    #pragma unroll
    for (int j = 0; j < 4; j++) {
        int h0 = hw0 + j * 8 + 2 * tig;
        gv2[j] = *reinterpret_cast<const float2*>(g_glob + (size_t)b * H_DIM + h0);
        ws2[j] = *reinterpret_cast<const float2*>(Ws + h0);
    }
    __syncthreads();

    const uint32_t abase = smem_u32(A_sm);
    const uint32_t a_off = (uint32_t)(lane & 15) * 80 + (uint32_t)(lane >> 4) * 16;

    #pragma unroll 1
    for (int m = 0; m < 8; m++) {
        mbar_wait((m & 1) ? mb1 : mb0, (m >> 1) & 1);
        __syncthreads();   // all warps done with the OTHER buffer -> safe to refill

        if (m + 1 < 8 && tid == 0) {
            uint32_t mb = ((m + 1) & 1) ? mb1 : mb0;
            mbar_expect_tx(mb, 16 * H_DIM * 4);
            uint32_t dst = e_base + (uint32_t)(((m + 1) & 1) * 16 * EPITCH) * 4;
            #pragma unroll
            for (int r = 0; r < 16; r++)
                bulk_g2s(dst + (uint32_t)(r * EPITCH) * 4,
                         enc + ((size_t)(t0 + (m + 1) * 16 + r) * B_DIM + b) * H_DIM,
                         H_DIM * 4, mb);
        }

        unsigned a0[4], a1[4];
        ldsm_x4(a0, abase + (uint32_t)m * 16 * 80 + a_off);
        ldsm_x4(a1, abase + (uint32_t)m * 16 * 80 + a_off + 32);

        const float* E = E_sm + (m & 1) * 16 * EPITCH;

        float c[4][4];
        #pragma unroll
        for (int j = 0; j < 4; j++) {
            c[j][0] = c[j][1] = c[j][2] = c[j][3] = 0.f;
            mma_bf16(c[j], a0, Bf[j][0]);
            mma_bf16(c[j], a1, Bf[j][1]);
        }

        float sum0 = 0.f, sum1 = 0.f;
        #pragma unroll
        for (int j = 0; j < 4; j++) {
            int h0 = hw0 + j * 8 + 2 * tig;
            float2 e0 = *reinterpret_cast<const float2*>(E + gid * EPITCH + h0);
            float2 e1 = *reinterpret_cast<const float2*>(E + (gid + 8) * EPITCH + h0);
            sum0 += ws2[j].x * tanh_ap(c[j][0] + e0.x + gv2[j].x)
                  + ws2[j].y * tanh_ap(c[j][1] + e0.y + gv2[j].y);
            sum1 += ws2[j].x * tanh_ap(c[j][2] + e1.x + gv2[j].x)
                  + ws2[j].y * tanh_ap(c[j][3] + e1.y + gv2[j].y);
        }
        sum0 += __shfl_xor_sync(0xFFFFFFFFu, sum0, 1);
        sum0 += __shfl_xor_sync(0xFFFFFFFFu, sum0, 2);
        sum1 += __shfl_xor_sync(0xFFFFFFFFu, sum1, 1);
        sum1 += __shfl_xor_sync(0xFFFFFFFFu, sum1, 2);
        if (tig == 0) {
            part[(m * 16 + gid) * 8 + wid]     = sum0;
            part[(m * 16 + gid + 8) * 8 + wid] = sum1;
        }
    }
    __syncthreads();

    // finalize: threads 0..127, one t each
    if (tid < 128) {
        const int t = t0 + tid;
        float s = 0.f;
        #pragma unroll
        for (int w = 0; w < 8; w++) s += part[tid * 8 + w];
        s += bsp[0];
        float e = __expf(s + mask[(size_t)t * B_DIM + b]);
        g_exp[(size_t)t * B_DIM + b] = e;

        float v = e;
        v += __shfl_xor_sync(0xFFFFFFFFu, v, 16);
        v += __shfl_xor_sync(0xFFFFFFFFu, v, 8);
        v += __shfl_xor_sync(0xFFFFFFFFu, v, 4);
        v += __shfl_xor_sync(0xFFFFFFFFu, v, 2);
        v += __shfl_xor_sync(0xFFFFFFFFu, v, 1);
        if (lane == 0) red4[wid] = v;
    }
    __syncthreads();
    if (tid == 0)
        g_part[(size_t)blockIdx.x * B_DIM + b] = red4[0] + red4[1] + red4[2] + red4[3];
}

// ============================================================================
// Kernel C: normalize
// ============================================================================
__global__ void __launch_bounds__(128) norm_kernel(float* __restrict__ out)
{
    __shared__ float inv_s;
    const int b = blockIdx.y;
    const int tid = threadIdx.x;

    if (tid < 32) {
        float v = g_part[(size_t)tid * B_DIM + b];
        v += __shfl_xor_sync(0xFFFFFFFFu, v, 16);
        v += __shfl_xor_sync(0xFFFFFFFFu, v, 8);
        v += __shfl_xor_sync(0xFFFFFFFFu, v, 4);
        v += __shfl_xor_sync(0xFFFFFFFFu, v, 2);
        v += __shfl_xor_sync(0xFFFFFFFFu, v, 1);
        if (tid == 0) inv_s = 1.0f / v;
    }
    __syncthreads();

    int t = blockIdx.x * 128 + tid;
    out[(size_t)t * B_DIM + b] = g_exp[(size_t)t * B_DIM + b] * inv_s;
}

// ============================================================================
extern "C" void kernel_launch(void* const* d_in, const int* in_sizes, int n_in,
                              void* d_out, int out_size)
{
    const float* enc  = (const float*)d_in[0];
    const float* mask = (const float*)d_in[1];
    const float* lm   = (const float*)d_in[2];
    const float* prev = (const float*)d_in[3];
    const float* Wk   = (const float*)d_in[4];
    const float* bk   = (const float*)d_in[5];
    const float* Wg   = (const float*)d_in[6];
    const float* bg   = (const float*)d_in[7];
    const float* Ws   = (const float*)d_in[8];
    const float* bs   = (const float*)d_in[9];
    float* out = (float*)d_out;

    static bool attr_set = false;
    if (!attr_set) {
        cudaFuncSetAttribute(gemm_tc_kernel,
                             cudaFuncAttributeMaxDynamicSharedMemorySize, GEMM_SMEM);
        cudaFuncSetAttribute(score_kernel,
                             cudaFuncAttributeMaxDynamicSharedMemorySize, SC_SMEM);
        attr_set = true;
    }

    gemm_tc_kernel<<<(K_DIM * H_DIM) / GR + H_DIM / GR, 128, GEMM_SMEM>>>(
        Wk, bk, Wg, bg, lm);
    score_kernel<<<dim3(T_DIM / T_BLK, B_DIM), 256, SC_SMEM>>>(enc, prev, mask, Ws, bs);
    norm_kernel<<<dim3(T_DIM / 128, B_DIM), 128>>>(out);
}